// round 5
// baseline (speedup 1.0000x reference)
#include <cuda_runtime.h>
#include <cuda_fp16.h>
#include <stdint.h>

// ---------------- problem constants ----------------
constexpr int kE   = 8;
constexpr int kH   = 1024;
constexpr int kF   = 4096;
constexpr int kDL  = 256;
constexpr int kTPE = 1024;
constexpr int kTok = kE * kTPE;   // 8192

// ---------------- tiling ----------------
constexpr int THREADS = 256;      // 8 warps
constexpr int BK = 64;

// gemm12: BM 256 x BN 128, warp tile 64x64 (wm = warp&3, wn = warp>>2)
constexpr int BM1 = 256, BN1 = 128, ST1 = 3;
// gemm3:  BM 128 x BN 128, warp tile 64x32 (wm = warp&1, wn = warp>>1)
constexpr int BM3 = 128, BN3 = 128, ST3 = 5;

constexpr int LDSA  = BK + 8;     // 72 halves (padded rows, conflict-free ldsm)
constexpr int LDSB  = BK + 8;     // 72 halves (NT B: [n][k])
constexpr int LDSB3 = BN3 + 8;    // 136 halves (NN B: [k][n])

constexpr int STG1 = BM1 * LDSA + BN1 * LDSB;   // 27648 halves / stage
constexpr int STG3 = BM3 * LDSA + BK * LDSB3;   // 17920 halves / stage
constexpr int STASH_U32 = 8 * 2048;             // 8 warps x 2048 u32 = 64 KB
constexpr int SMEM1 = ST1 * STG1 * 2 + STASH_U32 * 4;  // 231424 B (<= 232448)
constexpr int SMEM3 = ST3 * STG3 * 2;                  // 179200 B

// ---------------- fp16 scratch (device globals) ----------------
__device__ __half g_xh [(size_t)kTok * kH];        // 16 MB
__device__ __half g_ah [(size_t)kTok * kDL];       //  4 MB
__device__ __half g_wup[(size_t)kE * kF * kDL];    // 16 MB
__device__ __half g_v1 [(size_t)kE * kF * kH];     // 64 MB
__device__ __half g_w2 [(size_t)kE * kF * kH];     // 64 MB
__device__ __half g_hh [(size_t)kTok * kF];        // 64 MB  (silu(x1)*x2)

// ---------------- PTX helpers ----------------
__device__ __forceinline__ uint32_t smem_u32(const void* p) {
    uint32_t r;
    asm volatile("{ .reg .u64 t; cvta.to.shared.u64 t, %1; cvt.u32.u64 %0, t; }"
                 : "=r"(r) : "l"(p));
    return r;
}
__device__ __forceinline__ void cp16(uint32_t dst, const void* src) {
    asm volatile("cp.async.cg.shared.global [%0], [%1], 16;" :: "r"(dst), "l"(src));
}
__device__ __forceinline__ void cp_commit() { asm volatile("cp.async.commit_group;"); }
template <int N> __device__ __forceinline__ void cp_wait() {
    asm volatile("cp.async.wait_group %0;" :: "n"(N));
}
__device__ __forceinline__ void ldsm4(uint32_t* r, uint32_t a) {
    asm volatile("ldmatrix.sync.aligned.m8n8.x4.shared.b16 {%0,%1,%2,%3},[%4];"
                 : "=r"(r[0]), "=r"(r[1]), "=r"(r[2]), "=r"(r[3]) : "r"(a));
}
__device__ __forceinline__ void ldsm4t(uint32_t* r, uint32_t a) {
    asm volatile("ldmatrix.sync.aligned.m8n8.x4.trans.shared.b16 {%0,%1,%2,%3},[%4];"
                 : "=r"(r[0]), "=r"(r[1]), "=r"(r[2]), "=r"(r[3]) : "r"(a));
}
__device__ __forceinline__ void mma16816(float* c, const uint32_t* a, uint32_t b0, uint32_t b1) {
    asm volatile(
        "mma.sync.aligned.m16n8k16.row.col.f32.f16.f16.f32 "
        "{%0,%1,%2,%3},{%4,%5,%6,%7},{%8,%9},{%0,%1,%2,%3};"
        : "+f"(c[0]), "+f"(c[1]), "+f"(c[2]), "+f"(c[3])
        : "r"(a[0]), "r"(a[1]), "r"(a[2]), "r"(a[3]), "r"(b0), "r"(b1));
}

// ---------------- fused fp32 -> fp16 conversion (one launch) ----------------
__global__ void k_cvt_all(const float* __restrict__ x, const float* __restrict__ a,
                          const float* __restrict__ wu, const float* __restrict__ v,
                          const float* __restrict__ w) {
    constexpr size_t N1 = (size_t)kTok * kH / 4, N2 = (size_t)kTok * kDL / 4,
                     N3 = (size_t)kE * kF * kDL / 4, N4 = (size_t)kE * kF * kH / 4;
    constexpr size_t C1 = N1, C2 = C1 + N2, C3 = C2 + N3, C4 = C3 + N4, C5 = C4 + N4;
    for (size_t i = (size_t)blockIdx.x * blockDim.x + threadIdx.x; i < C5;
         i += (size_t)gridDim.x * blockDim.x) {
        const float4* s; __half2* d; size_t o;
        if      (i < C1) { s = (const float4*)x;  d = (__half2*)g_xh;  o = i;      }
        else if (i < C2) { s = (const float4*)a;  d = (__half2*)g_ah;  o = i - C1; }
        else if (i < C3) { s = (const float4*)wu; d = (__half2*)g_wup; o = i - C2; }
        else if (i < C4) { s = (const float4*)v;  d = (__half2*)g_v1;  o = i - C3; }
        else             { s = (const float4*)w;  d = (__half2*)g_w2;  o = i - C4; }
        float4 t = s[o];
        d[2 * o]     = __floats2half2_rn(t.x, t.y);
        d[2 * o + 1] = __floats2half2_rn(t.z, t.w);
    }
}

// ---------------- tile loaders (cp.async, 16B vectors, 256 threads) ----------------
__device__ __forceinline__ void load12(const __half* gA, int ldA, const __half* gB, int ldB,
                                       int kOff, __half* sA, __half* sB, int tid) {
    // A: 256 rows x 64 halves (2048 vec16); B: 128 rows x 64 halves (1024 vec16)
#pragma unroll
    for (int i = 0; i < 8; i++) {
        int v = tid + i * THREADS;
        int r = v >> 3, c = (v & 7) * 8;
        cp16(smem_u32(sA + r * LDSA + c), gA + (size_t)r * ldA + kOff + c);
    }
#pragma unroll
    for (int i = 0; i < 4; i++) {
        int v = tid + i * THREADS;
        int r = v >> 3, c = (v & 7) * 8;
        cp16(smem_u32(sB + r * LDSB + c), gB + (size_t)r * ldB + kOff + c);
    }
}

__device__ __forceinline__ void load3(const __half* gA, const __half* gB, int kOff,
                                      __half* sA, __half* sB, int tid) {
    // A: 128 rows x 64 halves (1024 vec16); B: 64 k-rows x 128 n-halves (1024 vec16)
#pragma unroll
    for (int i = 0; i < 4; i++) {
        int v = tid + i * THREADS;
        int r = v >> 3, c = (v & 7) * 8;
        cp16(smem_u32(sA + r * LDSA + c), gA + (size_t)r * kF + kOff + c);
    }
#pragma unroll
    for (int i = 0; i < 4; i++) {
        int v = tid + i * THREADS;
        int r = v >> 4, c = (v & 15) * 8;
        cp16(smem_u32(sB + r * LDSB3 + c), gB + (size_t)(kOff + r) * kH + c);
    }
}

// ---------------- warp-tile MMA: 64x64 NT (gemm12) ----------------
__device__ __forceinline__ void mma12(const __half* sA, const __half* sB,
                                      float (&acc)[4][8][4], int wm, int wn, int lane) {
#pragma unroll
    for (int kk = 0; kk < BK; kk += 16) {
        uint32_t a[4][4];
#pragma unroll
        for (int im = 0; im < 4; im++)
            ldsm4(a[im], smem_u32(sA + (wm * 64 + im * 16 + (lane & 15)) * LDSA
                                     + kk + (lane >> 4) * 8));
#pragma unroll
        for (int j = 0; j < 4; j++) {
            uint32_t b[4];
            ldsm4(b, smem_u32(sB + (wn * 64 + j * 16 + (lane & 7) + ((lane >> 4) << 3)) * LDSB
                                 + kk + ((lane >> 3) & 1) * 8));
#pragma unroll
            for (int im = 0; im < 4; im++) {
                mma16816(acc[im][2 * j],     a[im], b[0], b[1]);
                mma16816(acc[im][2 * j + 1], a[im], b[2], b[3]);
            }
        }
    }
}

// ---------------- warp-tile MMA: 64x32 NN (gemm3) ----------------
__device__ __forceinline__ void mma3(const __half* sA, const __half* sB,
                                     float (&acc)[4][4][4], int wm, int wn, int lane) {
#pragma unroll
    for (int kk = 0; kk < BK; kk += 16) {
        uint32_t a[4][4];
#pragma unroll
        for (int im = 0; im < 4; im++)
            ldsm4(a[im], smem_u32(sA + (wm * 64 + im * 16 + (lane & 15)) * LDSA
                                     + kk + (lane >> 4) * 8));
#pragma unroll
        for (int j = 0; j < 2; j++) {
            uint32_t b[4];
            ldsm4t(b, smem_u32(sB + (kk + (lane & 7) + ((lane >> 3) & 1) * 8) * LDSB3
                                  + wn * 32 + j * 16 + (lane >> 4) * 8));
#pragma unroll
            for (int im = 0; im < 4; im++) {
                mma16816(acc[im][2 * j],     a[im], b[0], b[1]);
                mma16816(acc[im][2 * j + 1], a[im], b[2], b[3]);
            }
        }
    }
}

// ==================== kernel 1: x1=acts@wup^T, x2=x@v1^T, h=silu(x1)*x2 ===========
__global__ void __launch_bounds__(THREADS, 1) k_gemm12() {
    extern __shared__ __half smem[];
    uint32_t* stash = (uint32_t*)(smem + ST1 * STG1);   // 8 warps x 2048 u32
    const int tid = threadIdx.x, lane = tid & 31, warp = tid >> 5;
    const int wm = warp & 3, wn = warp >> 2;
    const int nt = blockIdx.x, mt = blockIdx.y, e = blockIdx.z;

    const __half* A1 = g_ah  + (size_t)(e * kTPE + mt * BM1) * kDL;
    const __half* B1 = g_wup + ((size_t)e * kF + nt * BN1) * kDL;
    const __half* A2 = g_xh  + (size_t)(e * kTPE + mt * BM1) * kH;
    const __half* B2 = g_v1  + ((size_t)e * kF + nt * BN1) * kH;

    constexpr int NCH1 = kDL / BK;          // 4
    constexpr int NCH  = NCH1 + kH / BK;    // 20

    auto srcOf = [&](int c, const __half*& A, const __half*& B, int& la, int& lb, int& ko) {
        if (c < NCH1) { A = A1; B = B1; la = kDL; lb = kDL; ko = c * BK; }
        else          { A = A2; B = B2; la = kH;  lb = kH;  ko = (c - NCH1) * BK; }
    };

    float acc[4][8][4];
#pragma unroll
    for (int i = 0; i < 4; i++)
#pragma unroll
        for (int j = 0; j < 8; j++)
#pragma unroll
            for (int r = 0; r < 4; r++) acc[i][j][r] = 0.f;

    // prologue
#pragma unroll
    for (int c = 0; c < ST1 - 1; c++) {
        const __half *A, *B; int la, lb, ko;
        srcOf(c, A, B, la, lb, ko);
        __half* sb = smem + c * STG1;
        load12(A, la, B, lb, ko, sb, sb + BM1 * LDSA, tid);
        cp_commit();
    }

    for (int kc = 0; kc < NCH; kc++) {
        cp_wait<ST1 - 2>();
        __syncthreads();
        const int pf = kc + ST1 - 1;
        if (pf < NCH) {
            const __half *A, *B; int la, lb, ko;
            srcOf(pf, A, B, la, lb, ko);
            __half* sb = smem + (pf % ST1) * STG1;
            load12(A, la, B, lb, ko, sb, sb + BM1 * LDSA, tid);
        }
        cp_commit();

        if (kc == NCH1) {
            // gemm1 done: silu(x1) -> per-warp private smem stash (fp16), zero acc
#pragma unroll
            for (int im = 0; im < 4; im++)
#pragma unroll
                for (int jn = 0; jn < 8; jn++) {
#pragma unroll
                    for (int p = 0; p < 2; p++) {
                        float x0 = acc[im][jn][2 * p], x1 = acc[im][jn][2 * p + 1];
                        __half2 h2 = __floats2half2_rn(x0 / (1.f + __expf(-x0)),
                                                       x1 / (1.f + __expf(-x1)));
                        stash[warp * 2048 + ((im * 8 + jn) * 2 + p) * 32 + lane] =
                            *reinterpret_cast<uint32_t*>(&h2);
                    }
                    acc[im][jn][0] = acc[im][jn][1] = acc[im][jn][2] = acc[im][jn][3] = 0.f;
                }
        }

        __half* cs = smem + (kc % ST1) * STG1;
        mma12(cs, cs + BM1 * LDSA, acc, wm, wn, lane);
    }

    // epilogue: h = silu(x1) * x2 -> g_hh (fp16). Stash is warp-private: no sync needed.
    const int rBase = e * kTPE + mt * BM1 + wm * 64 + (lane >> 2);
    const int cBase = nt * BN1 + wn * 64 + (lane & 3) * 2;
#pragma unroll
    for (int im = 0; im < 4; im++)
#pragma unroll
        for (int jn = 0; jn < 8; jn++)
#pragma unroll
            for (int p = 0; p < 2; p++) {
                uint32_t sbits = stash[warp * 2048 + ((im * 8 + jn) * 2 + p) * 32 + lane];
                float2 sf = __half22float2(*reinterpret_cast<__half2*>(&sbits));
                int r = rBase + im * 16 + p * 8;
                int c = cBase + jn * 8;
                __half2 h2 = __floats2half2_rn(sf.x * acc[im][jn][2 * p],
                                               sf.y * acc[im][jn][2 * p + 1]);
                *reinterpret_cast<__half2*>(&g_hh[(size_t)r * kF + c]) = h2;
            }
}

// ==================== kernel 2: out = h @ w2 (NN) ====================
__global__ void __launch_bounds__(THREADS, 1) k_gemm3(float* __restrict__ out) {
    extern __shared__ __half smem[];
    const int tid = threadIdx.x, lane = tid & 31, warp = tid >> 5;
    const int wm = warp & 1, wn = warp >> 1;
    const int nt = blockIdx.x, mt = blockIdx.y, e = blockIdx.z;

    const __half* A = g_hh + (size_t)(e * kTPE + mt * BM3) * kF;
    const __half* B = g_w2 + (size_t)e * kF * kH + nt * BN3;
    constexpr int NCH = kF / BK;   // 64

    float acc[4][4][4];
#pragma unroll
    for (int i = 0; i < 4; i++)
#pragma unroll
        for (int j = 0; j < 4; j++)
#pragma unroll
            for (int r = 0; r < 4; r++) acc[i][j][r] = 0.f;

#pragma unroll
    for (int c = 0; c < ST3 - 1; c++) {
        __half* sb = smem + c * STG3;
        load3(A, B, c * BK, sb, sb + BM3 * LDSA, tid);
        cp_commit();
    }

    for (int kc = 0; kc < NCH; kc++) {
        cp_wait<ST3 - 2>();
        __syncthreads();
        const int pf = kc + ST3 - 1;
        if (pf < NCH) {
            __half* sb = smem + (pf % ST3) * STG3;
            load3(A, B, pf * BK, sb, sb + BM3 * LDSA, tid);
        }
        cp_commit();
        __half* cs = smem + (kc % ST3) * STG3;
        mma3(cs, cs + BM3 * LDSA, acc, wm, wn, lane);
    }

    const int rBase = e * kTPE + mt * BM3 + wm * 64 + (lane >> 2);
    const int cBase = nt * BN3 + wn * 32 + (lane & 3) * 2;
#pragma unroll
    for (int im = 0; im < 4; im++)
#pragma unroll
        for (int jn = 0; jn < 4; jn++)
#pragma unroll
            for (int p = 0; p < 2; p++) {
                int r = rBase + im * 16 + p * 8;
                int c = cBase + jn * 8;
                *reinterpret_cast<float2*>(&out[(size_t)r * kH + c]) =
                    make_float2(acc[im][jn][2 * p], acc[im][jn][2 * p + 1]);
            }
}

// ---------------- launch ----------------
extern "C" void kernel_launch(void* const* d_in, const int* in_sizes, int n_in,
                              void* d_out, int out_size) {
    const float* x    = (const float*)d_in[0];
    const float* acts = (const float*)d_in[1];
    const float* wup  = (const float*)d_in[2];
    const float* v1   = (const float*)d_in[3];
    const float* w2   = (const float*)d_in[4];
    float* out = (float*)d_out;

    cudaFuncSetAttribute(k_gemm12, cudaFuncAttributeMaxDynamicSharedMemorySize, SMEM1);
    cudaFuncSetAttribute(k_gemm3,  cudaFuncAttributeMaxDynamicSharedMemorySize, SMEM3);

    k_cvt_all<<<1184, 256>>>(x, acts, wup, v1, w2);

    dim3 g12(kF / BN1, kTPE / BM1, kE);   // 32 x 4 x 8 = 1024 CTAs
    k_gemm12<<<g12, THREADS, SMEM1>>>();

    dim3 g3(kH / BN3, kTPE / BM3, kE);    // 8 x 8 x 8 = 512 CTAs
    k_gemm3<<<g3, THREADS, SMEM3>>>(out);
}

// round 6
// speedup vs baseline: 1.1102x; 1.1102x over previous
#include <cuda_runtime.h>
#include <cuda_fp16.h>
#include <stdint.h>

// ---------------- problem constants ----------------
constexpr int kE   = 8;
constexpr int kH   = 1024;
constexpr int kF   = 4096;
constexpr int kDL  = 256;
constexpr int kTPE = 1024;
constexpr int kTok = kE * kTPE;   // 8192

// ---------------- tiling (R4 geometry: 16 warps, warp tile 32x64) ----------------
constexpr int BM = 128, BN = 256, BK = 64;
constexpr int THREADS = 512;      // 16 warps: 4 (M) x 4 (N)
constexpr int ST1 = 4;            // stages gemm12
constexpr int ST3 = 4;            // stages gemm3

constexpr int LDSA  = BK + 8;     // 72 halves per A row
constexpr int LDSB  = BK + 8;     // 72 halves per B row (NT: [n][k])
constexpr int LDSB3 = BN + 8;     // 264 halves per B row (NN: [k][n])

constexpr int STG12 = BM * LDSA + BN * LDSB;   // 27648 halves / stage
constexpr int STG3  = BM * LDSA + BK * LDSB3;  // 26112 halves / stage
constexpr int SMEM12 = ST1 * STG12 * 2;        // 221184 B
constexpr int SMEM3  = ST3 * STG3  * 2;        // 208896 B

// ---------------- fp16 scratch (device globals: no allocation allowed) ----------------
__device__ __half g_xh [(size_t)kTok * kH];        // 16 MB
__device__ __half g_ah [(size_t)kTok * kDL];       //  4 MB
__device__ __half g_wup[(size_t)kE * kF * kDL];    // 16 MB
__device__ __half g_v1 [(size_t)kE * kF * kH];     // 64 MB
__device__ __half g_w2 [(size_t)kE * kF * kH];     // 64 MB
__device__ __half g_hh [(size_t)kTok * kF];        // 64 MB  (silu(x1)*x2)

// ---------------- PTX helpers ----------------
__device__ __forceinline__ uint32_t smem_u32(const void* p) {
    uint32_t r;
    asm volatile("{ .reg .u64 t; cvta.to.shared.u64 t, %1; cvt.u32.u64 %0, t; }"
                 : "=r"(r) : "l"(p));
    return r;
}
__device__ __forceinline__ void cp16(uint32_t dst, const void* src) {
    asm volatile("cp.async.cg.shared.global [%0], [%1], 16;" :: "r"(dst), "l"(src));
}
__device__ __forceinline__ void cp_commit() { asm volatile("cp.async.commit_group;"); }
template <int N> __device__ __forceinline__ void cp_wait() {
    asm volatile("cp.async.wait_group %0;" :: "n"(N));
}
__device__ __forceinline__ void ldsm4(uint32_t* r, uint32_t a) {
    asm volatile("ldmatrix.sync.aligned.m8n8.x4.shared.b16 {%0,%1,%2,%3},[%4];"
                 : "=r"(r[0]), "=r"(r[1]), "=r"(r[2]), "=r"(r[3]) : "r"(a));
}
__device__ __forceinline__ void ldsm4t(uint32_t* r, uint32_t a) {
    asm volatile("ldmatrix.sync.aligned.m8n8.x4.trans.shared.b16 {%0,%1,%2,%3},[%4];"
                 : "=r"(r[0]), "=r"(r[1]), "=r"(r[2]), "=r"(r[3]) : "r"(a));
}
__device__ __forceinline__ void mma16816(float* c, const uint32_t* a, uint32_t b0, uint32_t b1) {
    asm volatile(
        "mma.sync.aligned.m16n8k16.row.col.f32.f16.f16.f32 "
        "{%0,%1,%2,%3},{%4,%5,%6,%7},{%8,%9},{%0,%1,%2,%3};"
        : "+f"(c[0]), "+f"(c[1]), "+f"(c[2]), "+f"(c[3])
        : "r"(a[0]), "r"(a[1]), "r"(a[2]), "r"(a[3]), "r"(b0), "r"(b1));
}

// ---------------- fused fp32 -> fp16 conversion (one launch) ----------------
__global__ void k_cvt_all(const float* __restrict__ x, const float* __restrict__ a,
                          const float* __restrict__ wu, const float* __restrict__ v,
                          const float* __restrict__ w) {
    constexpr size_t N1 = (size_t)kTok * kH / 4, N2 = (size_t)kTok * kDL / 4,
                     N3 = (size_t)kE * kF * kDL / 4, N4 = (size_t)kE * kF * kH / 4;
    constexpr size_t C1 = N1, C2 = C1 + N2, C3 = C2 + N3, C4 = C3 + N4, C5 = C4 + N4;
    for (size_t i = (size_t)blockIdx.x * blockDim.x + threadIdx.x; i < C5;
         i += (size_t)gridDim.x * blockDim.x) {
        const float4* s; __half2* d; size_t o;
        if      (i < C1) { s = (const float4*)x;  d = (__half2*)g_xh;  o = i;      }
        else if (i < C2) { s = (const float4*)a;  d = (__half2*)g_ah;  o = i - C1; }
        else if (i < C3) { s = (const float4*)wu; d = (__half2*)g_wup; o = i - C2; }
        else if (i < C4) { s = (const float4*)v;  d = (__half2*)g_v1;  o = i - C3; }
        else             { s = (const float4*)w;  d = (__half2*)g_w2;  o = i - C4; }
        float4 t = s[o];
        d[2 * o]     = __floats2half2_rn(t.x, t.y);
        d[2 * o + 1] = __floats2half2_rn(t.z, t.w);
    }
}

// ---------------- tile loaders (cp.async, 16B vectors, 512 threads) ----------------
__device__ __forceinline__ void load_nt(const __half* gA, int ldA, const __half* gB, int ldB,
                                        int kBase, __half* sA, __half* sB, int tid) {
    // A: 128 rows x 64 halves (1024 vec16); B: 256 rows x 64 halves (2048 vec16)
#pragma unroll
    for (int i = 0; i < 2; i++) {
        int v = tid + i * THREADS;
        int row = v >> 3, c = (v & 7) * 8;
        cp16(smem_u32(sA + row * LDSA + c), gA + (size_t)row * ldA + kBase + c);
    }
#pragma unroll
    for (int i = 0; i < 4; i++) {
        int v = tid + i * THREADS;
        int row = v >> 3, c = (v & 7) * 8;
        cp16(smem_u32(sB + row * LDSB + c), gB + (size_t)row * ldB + kBase + c);
    }
}

__device__ __forceinline__ void load_nn(const __half* gA, int ldA, const __half* gB, int ldB,
                                        int kBase, __half* sA, __half* sB, int tid) {
    // A: 128 rows x 64 halves. B: 64 k-rows x 256 n-halves (2048 vec16).
#pragma unroll
    for (int i = 0; i < 2; i++) {
        int v = tid + i * THREADS;
        int row = v >> 3, c = (v & 7) * 8;
        cp16(smem_u32(sA + row * LDSA + c), gA + (size_t)row * ldA + kBase + c);
    }
#pragma unroll
    for (int i = 0; i < 4; i++) {
        int v = tid + i * THREADS;
        int row = v >> 5, c = (v & 31) * 8;
        cp16(smem_u32(sB + row * LDSB3 + c), gB + (size_t)(kBase + row) * ldB + c);
    }
}

// ---------------- per-chunk MMA (warp tile 32x64: 2 m-tiles x 8 n-tiles) ----------------
__device__ __forceinline__ void mma_nt(const __half* sA, const __half* sB,
                                       float (&acc)[2][8][4], int wm, int wn, int lane) {
#pragma unroll
    for (int kk = 0; kk < BK; kk += 16) {
        uint32_t a[2][4];
#pragma unroll
        for (int im = 0; im < 2; im++) {
            const __half* p = sA + (wm * 32 + im * 16 + (lane & 15)) * LDSA + kk + (lane >> 4) * 8;
            ldsm4(a[im], smem_u32(p));
        }
#pragma unroll
        for (int j = 0; j < 4; j++) {
            const __half* p = sB + (wn * 64 + j * 16 + (lane & 7) + ((lane >> 4) << 3)) * LDSB
                               + kk + ((lane >> 3) & 1) * 8;
            uint32_t b[4];
            ldsm4(b, smem_u32(p));
#pragma unroll
            for (int im = 0; im < 2; im++) {
                mma16816(acc[im][2 * j],     a[im], b[0], b[1]);
                mma16816(acc[im][2 * j + 1], a[im], b[2], b[3]);
            }
        }
    }
}

__device__ __forceinline__ void mma_nn(const __half* sA, const __half* sB,
                                       float (&acc)[2][8][4], int wm, int wn, int lane) {
#pragma unroll
    for (int kk = 0; kk < BK; kk += 16) {
        uint32_t a[2][4];
#pragma unroll
        for (int im = 0; im < 2; im++) {
            const __half* p = sA + (wm * 32 + im * 16 + (lane & 15)) * LDSA + kk + (lane >> 4) * 8;
            ldsm4(a[im], smem_u32(p));
        }
#pragma unroll
        for (int j = 0; j < 4; j++) {
            const __half* p = sB + (kk + (lane & 7) + ((lane >> 3) & 1) * 8) * LDSB3
                               + wn * 64 + j * 16 + (lane >> 4) * 8;
            uint32_t b[4];
            ldsm4t(b, smem_u32(p));
#pragma unroll
            for (int im = 0; im < 2; im++) {
                mma16816(acc[im][2 * j],     a[im], b[0], b[1]);
                mma16816(acc[im][2 * j + 1], a[im], b[2], b[3]);
            }
        }
    }
}

// ==================== kernel 1: x1=acts@wup^T, x2=x@v1^T, h=silu(x1)*x2 ===========
__global__ void __launch_bounds__(THREADS, 1) k_gemm12() {
    extern __shared__ __half smem[];
    const int tid = threadIdx.x, lane = tid & 31, warp = tid >> 5;
    const int wm = warp & 3, wn = warp >> 2;
    const int nt = blockIdx.x, mt = blockIdx.y, e = blockIdx.z;

    const __half* A1 = g_ah  + (size_t)(e * kTPE + mt * BM) * kDL;
    const __half* B1 = g_wup + ((size_t)e * kF + nt * BN) * kDL;
    const __half* A2 = g_xh  + (size_t)(e * kTPE + mt * BM) * kH;
    const __half* B2 = g_v1  + ((size_t)e * kF + nt * BN) * kH;

    constexpr int NCH1 = kDL / BK;          // 4
    constexpr int NCH  = NCH1 + kH / BK;    // 20

    auto srcOf = [&](int c, const __half*& A, const __half*& B, int& la, int& lb, int& ko) {
        if (c < NCH1) { A = A1; B = B1; la = kDL; lb = kDL; ko = c * BK; }
        else          { A = A2; B = B2; la = kH;  lb = kH;  ko = (c - NCH1) * BK; }
    };

    float acc[2][8][4];
#pragma unroll
    for (int i = 0; i < 2; i++)
#pragma unroll
        for (int j = 0; j < 8; j++)
#pragma unroll
            for (int r = 0; r < 4; r++) acc[i][j][r] = 0.f;
    __half2 sf[2][8][2];

    // prologue: stages 0..ST1-2
#pragma unroll
    for (int c = 0; c < ST1 - 1; c++) {
        const __half *A, *B; int la, lb, ko;
        srcOf(c, A, B, la, lb, ko);
        __half* sb = smem + c * STG12;
        load_nt(A, la, B, lb, ko, sb, sb + BM * LDSA, tid);
        cp_commit();
    }

    for (int kc = 0; kc < NCH; kc++) {
        cp_wait<ST1 - 2>();
        __syncthreads();
        const int pf = kc + ST1 - 1;
        if (pf < NCH) {
            const __half *A, *B; int la, lb, ko;
            srcOf(pf, A, B, la, lb, ko);
            __half* sb = smem + (pf % ST1) * STG12;
            load_nt(A, la, B, lb, ko, sb, sb + BM * LDSA, tid);
        }
        cp_commit();

        if (kc == NCH1) {
            // acc holds x1 (gemm1 complete). silu -> fp16 regs, reset acc for gemm2.
#pragma unroll
            for (int i = 0; i < 2; i++)
#pragma unroll
                for (int j = 0; j < 8; j++) {
#pragma unroll
                    for (int p = 0; p < 2; p++) {
                        float x0 = acc[i][j][2 * p], x1 = acc[i][j][2 * p + 1];
                        sf[i][j][p] = __floats2half2_rn(x0 / (1.f + __expf(-x0)),
                                                        x1 / (1.f + __expf(-x1)));
                    }
                    acc[i][j][0] = acc[i][j][1] = acc[i][j][2] = acc[i][j][3] = 0.f;
                }
        }

        __half* cs = smem + (kc % ST1) * STG12;
        mma_nt(cs, cs + BM * LDSA, acc, wm, wn, lane);
    }

    // epilogue: h = silu(x1) * x2 -> fp16 scratch
    const int rBase = e * kTPE + mt * BM + wm * 32 + (lane >> 2);
    const int cBase = nt * BN + wn * 64 + (lane & 3) * 2;
#pragma unroll
    for (int i = 0; i < 2; i++)
#pragma unroll
        for (int j = 0; j < 8; j++) {
            int r = rBase + i * 16;
            int c = cBase + j * 8;
            float2 s0 = __half22float2(sf[i][j][0]);
            float2 s1 = __half22float2(sf[i][j][1]);
            __half2 h0 = __floats2half2_rn(s0.x * acc[i][j][0], s0.y * acc[i][j][1]);
            __half2 h1 = __floats2half2_rn(s1.x * acc[i][j][2], s1.y * acc[i][j][3]);
            *reinterpret_cast<__half2*>(&g_hh[(size_t)r * kF + c])       = h0;
            *reinterpret_cast<__half2*>(&g_hh[(size_t)(r + 8) * kF + c]) = h1;
        }
}

// ==================== kernel 2: out = h @ w2 (NN) ====================
__global__ void __launch_bounds__(THREADS, 1) k_gemm3(float* __restrict__ out) {
    extern __shared__ __half smem[];
    const int tid = threadIdx.x, lane = tid & 31, warp = tid >> 5;
    const int wm = warp & 3, wn = warp >> 2;
    const int nt = blockIdx.x, mt = blockIdx.y, e = blockIdx.z;

    const __half* A = g_hh + (size_t)(e * kTPE + mt * BM) * kF;
    const __half* B = g_w2 + (size_t)e * kF * kH + nt * BN;
    constexpr int NCH = kF / BK;   // 64

    float acc[2][8][4];
#pragma unroll
    for (int i = 0; i < 2; i++)
#pragma unroll
        for (int j = 0; j < 8; j++)
#pragma unroll
            for (int r = 0; r < 4; r++) acc[i][j][r] = 0.f;

#pragma unroll
    for (int c = 0; c < ST3 - 1; c++) {
        __half* sb = smem + c * STG3;
        load_nn(A, kF, B, kH, c * BK, sb, sb + BM * LDSA, tid);
        cp_commit();
    }

    for (int kc = 0; kc < NCH; kc++) {
        cp_wait<ST3 - 2>();
        __syncthreads();
        const int pf = kc + ST3 - 1;
        if (pf < NCH) {
            __half* sb = smem + (pf % ST3) * STG3;
            load_nn(A, kF, B, kH, pf * BK, sb, sb + BM * LDSA, tid);
        }
        cp_commit();
        __half* cs = smem + (kc % ST3) * STG3;
        mma_nn(cs, cs + BM * LDSA, acc, wm, wn, lane);
    }

    const int rBase = e * kTPE + mt * BM + wm * 32 + (lane >> 2);
    const int cBase = nt * BN + wn * 64 + (lane & 3) * 2;
#pragma unroll
    for (int i = 0; i < 2; i++)
#pragma unroll
        for (int j = 0; j < 8; j++) {
            int r = rBase + i * 16;
            int c = cBase + j * 8;
            *reinterpret_cast<float2*>(&out[(size_t)r * kH + c]) =
                make_float2(acc[i][j][0], acc[i][j][1]);
            *reinterpret_cast<float2*>(&out[(size_t)(r + 8) * kH + c]) =
                make_float2(acc[i][j][2], acc[i][j][3]);
        }
}

// ---------------- launch ----------------
extern "C" void kernel_launch(void* const* d_in, const int* in_sizes, int n_in,
                              void* d_out, int out_size) {
    const float* x    = (const float*)d_in[0];
    const float* acts = (const float*)d_in[1];
    const float* wup  = (const float*)d_in[2];
    const float* v1   = (const float*)d_in[3];
    const float* w2   = (const float*)d_in[4];
    float* out = (float*)d_out;

    cudaFuncSetAttribute(k_gemm12, cudaFuncAttributeMaxDynamicSharedMemorySize, SMEM12);
    cudaFuncSetAttribute(k_gemm3,  cudaFuncAttributeMaxDynamicSharedMemorySize, SMEM3);

    k_cvt_all<<<1184, 256>>>(x, acts, wup, v1, w2);

    dim3 g12(kF / BN, kTPE / BM, kE);   // 16 x 8 x 8 = 1024 CTAs
    k_gemm12<<<g12, THREADS, SMEM12>>>();

    dim3 g3(kH / BN, kTPE / BM, kE);    // 4 x 8 x 8 = 256 CTAs
    k_gemm3<<<g3, THREADS, SMEM3>>>(out);
}

// round 7
// speedup vs baseline: 1.1293x; 1.0172x over previous
#include <cuda_runtime.h>
#include <cuda_fp16.h>
#include <stdint.h>

// ---------------- problem constants ----------------
constexpr int kE   = 8;
constexpr int kH   = 1024;
constexpr int kF   = 4096;
constexpr int kDL  = 256;
constexpr int kTPE = 1024;
constexpr int kTok = kE * kTPE;   // 8192

// ---------------- tiling: 128x128 CTAs, 8 warps, 2 CTAs/SM ----------------
constexpr int BM = 128, BN = 128, BK = 64;
constexpr int THREADS = 256;      // 8 warps: 4 (M) x 2 (N), warp tile 32x64
constexpr int ST1 = 3;            // stages gemm12
constexpr int ST3 = 3;            // stages gemm3

constexpr int LDSA  = BK + 8;     // 72 halves per A row
constexpr int LDSB  = BK + 8;     // 72 halves per B row (NT: [n][k])
constexpr int LDSB3 = BN + 8;     // 136 halves per B row (NN: [k][n])

constexpr int STG12 = BM * LDSA + BN * LDSB;   // 18432 halves / stage
constexpr int STG3  = BM * LDSA + BK * LDSB3;  // 17920 halves / stage
constexpr int SMEM12 = ST1 * STG12 * 2;        // 110592 B  (x2 CTA = 221184)
constexpr int SMEM3  = ST3 * STG3  * 2;        // 107520 B  (x2 CTA = 215040)

// ---------------- fp16 scratch (device globals: no allocation allowed) ----------------
__device__ __half g_xh [(size_t)kTok * kH];        // 16 MB
__device__ __half g_ah [(size_t)kTok * kDL];       //  4 MB
__device__ __half g_wup[(size_t)kE * kF * kDL];    // 16 MB
__device__ __half g_v1 [(size_t)kE * kF * kH];     // 64 MB
__device__ __half g_w2 [(size_t)kE * kF * kH];     // 64 MB
__device__ __half g_hh [(size_t)kTok * kF];        // 64 MB  (silu(x1)*x2)

// ---------------- PTX helpers ----------------
__device__ __forceinline__ uint32_t smem_u32(const void* p) {
    uint32_t r;
    asm volatile("{ .reg .u64 t; cvta.to.shared.u64 t, %1; cvt.u32.u64 %0, t; }"
                 : "=r"(r) : "l"(p));
    return r;
}
__device__ __forceinline__ void cp16(uint32_t dst, const void* src) {
    asm volatile("cp.async.cg.shared.global [%0], [%1], 16;" :: "r"(dst), "l"(src));
}
__device__ __forceinline__ void cp_commit() { asm volatile("cp.async.commit_group;"); }
template <int N> __device__ __forceinline__ void cp_wait() {
    asm volatile("cp.async.wait_group %0;" :: "n"(N));
}
__device__ __forceinline__ void ldsm4(uint32_t* r, uint32_t a) {
    asm volatile("ldmatrix.sync.aligned.m8n8.x4.shared.b16 {%0,%1,%2,%3},[%4];"
                 : "=r"(r[0]), "=r"(r[1]), "=r"(r[2]), "=r"(r[3]) : "r"(a));
}
__device__ __forceinline__ void ldsm4t(uint32_t* r, uint32_t a) {
    asm volatile("ldmatrix.sync.aligned.m8n8.x4.trans.shared.b16 {%0,%1,%2,%3},[%4];"
                 : "=r"(r[0]), "=r"(r[1]), "=r"(r[2]), "=r"(r[3]) : "r"(a));
}
__device__ __forceinline__ void mma16816(float* c, const uint32_t* a, uint32_t b0, uint32_t b1) {
    asm volatile(
        "mma.sync.aligned.m16n8k16.row.col.f32.f16.f16.f32 "
        "{%0,%1,%2,%3},{%4,%5,%6,%7},{%8,%9},{%0,%1,%2,%3};"
        : "+f"(c[0]), "+f"(c[1]), "+f"(c[2]), "+f"(c[3])
        : "r"(a[0]), "r"(a[1]), "r"(a[2]), "r"(a[3]), "r"(b0), "r"(b1));
}

// ---------------- fused fp32 -> fp16 conversion (one launch) ----------------
__global__ void k_cvt_all(const float* __restrict__ x, const float* __restrict__ a,
                          const float* __restrict__ wu, const float* __restrict__ v,
                          const float* __restrict__ w) {
    constexpr size_t N1 = (size_t)kTok * kH / 4, N2 = (size_t)kTok * kDL / 4,
                     N3 = (size_t)kE * kF * kDL / 4, N4 = (size_t)kE * kF * kH / 4;
    constexpr size_t C1 = N1, C2 = C1 + N2, C3 = C2 + N3, C4 = C3 + N4, C5 = C4 + N4;
    for (size_t i = (size_t)blockIdx.x * blockDim.x + threadIdx.x; i < C5;
         i += (size_t)gridDim.x * blockDim.x) {
        const float4* s; __half2* d; size_t o;
        if      (i < C1) { s = (const float4*)x;  d = (__half2*)g_xh;  o = i;      }
        else if (i < C2) { s = (const float4*)a;  d = (__half2*)g_ah;  o = i - C1; }
        else if (i < C3) { s = (const float4*)wu; d = (__half2*)g_wup; o = i - C2; }
        else if (i < C4) { s = (const float4*)v;  d = (__half2*)g_v1;  o = i - C3; }
        else             { s = (const float4*)w;  d = (__half2*)g_w2;  o = i - C4; }
        float4 t = s[o];
        d[2 * o]     = __floats2half2_rn(t.x, t.y);
        d[2 * o + 1] = __floats2half2_rn(t.z, t.w);
    }
}

// ---------------- tile loaders (cp.async, 16B vectors, 256 threads) ----------------
__device__ __forceinline__ void load_nt(const __half* gA, int ldA, const __half* gB, int ldB,
                                        int kBase, __half* sA, __half* sB, int tid) {
    // A: 128 rows x 64 halves (1024 vec16); B: 128 rows x 64 halves (1024 vec16)
#pragma unroll
    for (int i = 0; i < 4; i++) {
        int v = tid + i * THREADS;
        int row = v >> 3, c = (v & 7) * 8;
        cp16(smem_u32(sA + row * LDSA + c), gA + (size_t)row * ldA + kBase + c);
    }
#pragma unroll
    for (int i = 0; i < 4; i++) {
        int v = tid + i * THREADS;
        int row = v >> 3, c = (v & 7) * 8;
        cp16(smem_u32(sB + row * LDSB + c), gB + (size_t)row * ldB + kBase + c);
    }
}

__device__ __forceinline__ void load_nn(const __half* gA, int ldA, const __half* gB, int ldB,
                                        int kBase, __half* sA, __half* sB, int tid) {
    // A: 128 rows x 64 halves. B: 64 k-rows x 128 n-halves (1024 vec16).
#pragma unroll
    for (int i = 0; i < 4; i++) {
        int v = tid + i * THREADS;
        int row = v >> 3, c = (v & 7) * 8;
        cp16(smem_u32(sA + row * LDSA + c), gA + (size_t)row * ldA + kBase + c);
    }
#pragma unroll
    for (int i = 0; i < 4; i++) {
        int v = tid + i * THREADS;
        int row = v >> 4, c = (v & 15) * 8;
        cp16(smem_u32(sB + row * LDSB3 + c), gB + (size_t)(kBase + row) * ldB + c);
    }
}

// ---------------- per-chunk MMA (warp tile 32x64: 2 m-tiles x 8 n-tiles) ----------------
__device__ __forceinline__ void mma_nt(const __half* sA, const __half* sB,
                                       float (&acc)[2][8][4], int wm, int wn, int lane) {
#pragma unroll
    for (int kk = 0; kk < BK; kk += 16) {
        uint32_t a[2][4];
#pragma unroll
        for (int im = 0; im < 2; im++) {
            const __half* p = sA + (wm * 32 + im * 16 + (lane & 15)) * LDSA + kk + (lane >> 4) * 8;
            ldsm4(a[im], smem_u32(p));
        }
#pragma unroll
        for (int j = 0; j < 4; j++) {
            const __half* p = sB + (wn * 64 + j * 16 + (lane & 7) + ((lane >> 4) << 3)) * LDSB
                               + kk + ((lane >> 3) & 1) * 8;
            uint32_t b[4];
            ldsm4(b, smem_u32(p));
#pragma unroll
            for (int im = 0; im < 2; im++) {
                mma16816(acc[im][2 * j],     a[im], b[0], b[1]);
                mma16816(acc[im][2 * j + 1], a[im], b[2], b[3]);
            }
        }
    }
}

__device__ __forceinline__ void mma_nn(const __half* sA, const __half* sB,
                                       float (&acc)[2][8][4], int wm, int wn, int lane) {
#pragma unroll
    for (int kk = 0; kk < BK; kk += 16) {
        uint32_t a[2][4];
#pragma unroll
        for (int im = 0; im < 2; im++) {
            const __half* p = sA + (wm * 32 + im * 16 + (lane & 15)) * LDSA + kk + (lane >> 4) * 8;
            ldsm4(a[im], smem_u32(p));
        }
#pragma unroll
        for (int j = 0; j < 4; j++) {
            const __half* p = sB + (kk + (lane & 7) + ((lane >> 3) & 1) * 8) * LDSB3
                               + wn * 64 + j * 16 + (lane >> 4) * 8;
            uint32_t b[4];
            ldsm4t(b, smem_u32(p));
#pragma unroll
            for (int im = 0; im < 2; im++) {
                mma16816(acc[im][2 * j],     a[im], b[0], b[1]);
                mma16816(acc[im][2 * j + 1], a[im], b[2], b[3]);
            }
        }
    }
}

// ==================== kernel 1: x1=acts@wup^T, x2=x@v1^T, h=silu(x1)*x2 ===========
__global__ void __launch_bounds__(THREADS, 2) k_gemm12() {
    extern __shared__ __half smem[];
    const int tid = threadIdx.x, lane = tid & 31, warp = tid >> 5;
    const int wm = warp & 3, wn = warp >> 2;
    const int nt = blockIdx.x, mt = blockIdx.y, e = blockIdx.z;

    const __half* A1 = g_ah  + (size_t)(e * kTPE + mt * BM) * kDL;
    const __half* B1 = g_wup + ((size_t)e * kF + nt * BN) * kDL;
    const __half* A2 = g_xh  + (size_t)(e * kTPE + mt * BM) * kH;
    const __half* B2 = g_v1  + ((size_t)e * kF + nt * BN) * kH;

    constexpr int NCH1 = kDL / BK;          // 4
    constexpr int NCH  = NCH1 + kH / BK;    // 20

    auto srcOf = [&](int c, const __half*& A, const __half*& B, int& la, int& lb, int& ko) {
        if (c < NCH1) { A = A1; B = B1; la = kDL; lb = kDL; ko = c * BK; }
        else          { A = A2; B = B2; la = kH;  lb = kH;  ko = (c - NCH1) * BK; }
    };

    float acc[2][8][4];
#pragma unroll
    for (int i = 0; i < 2; i++)
#pragma unroll
        for (int j = 0; j < 8; j++)
#pragma unroll
            for (int r = 0; r < 4; r++) acc[i][j][r] = 0.f;
    __half2 sf[2][8][2];

    // prologue: stages 0..ST1-2
#pragma unroll
    for (int c = 0; c < ST1 - 1; c++) {
        const __half *A, *B; int la, lb, ko;
        srcOf(c, A, B, la, lb, ko);
        __half* sb = smem + c * STG12;
        load_nt(A, la, B, lb, ko, sb, sb + BM * LDSA, tid);
        cp_commit();
    }

    for (int kc = 0; kc < NCH; kc++) {
        cp_wait<ST1 - 2>();
        __syncthreads();
        const int pf = kc + ST1 - 1;
        if (pf < NCH) {
            const __half *A, *B; int la, lb, ko;
            srcOf(pf, A, B, la, lb, ko);
            __half* sb = smem + (pf % ST1) * STG12;
            load_nt(A, la, B, lb, ko, sb, sb + BM * LDSA, tid);
        }
        cp_commit();

        if (kc == NCH1) {
            // acc holds x1 (gemm1 complete). silu -> fp16 regs, reset acc for gemm2.
#pragma unroll
            for (int i = 0; i < 2; i++)
#pragma unroll
                for (int j = 0; j < 8; j++) {
#pragma unroll
                    for (int p = 0; p < 2; p++) {
                        float x0 = acc[i][j][2 * p], x1 = acc[i][j][2 * p + 1];
                        sf[i][j][p] = __floats2half2_rn(x0 / (1.f + __expf(-x0)),
                                                        x1 / (1.f + __expf(-x1)));
                    }
                    acc[i][j][0] = acc[i][j][1] = acc[i][j][2] = acc[i][j][3] = 0.f;
                }
        }

        __half* cs = smem + (kc % ST1) * STG12;
        mma_nt(cs, cs + BM * LDSA, acc, wm, wn, lane);
    }

    // epilogue: h = silu(x1) * x2 -> fp16 scratch
    const int rBase = e * kTPE + mt * BM + wm * 32 + (lane >> 2);
    const int cBase = nt * BN + wn * 64 + (lane & 3) * 2;
#pragma unroll
    for (int i = 0; i < 2; i++)
#pragma unroll
        for (int j = 0; j < 8; j++) {
            int r = rBase + i * 16;
            int c = cBase + j * 8;
            float2 s0 = __half22float2(sf[i][j][0]);
            float2 s1 = __half22float2(sf[i][j][1]);
            __half2 h0 = __floats2half2_rn(s0.x * acc[i][j][0], s0.y * acc[i][j][1]);
            __half2 h1 = __floats2half2_rn(s1.x * acc[i][j][2], s1.y * acc[i][j][3]);
            *reinterpret_cast<__half2*>(&g_hh[(size_t)r * kF + c])       = h0;
            *reinterpret_cast<__half2*>(&g_hh[(size_t)(r + 8) * kF + c]) = h1;
        }
}

// ==================== kernel 2: out = h @ w2 (NN) ====================
__global__ void __launch_bounds__(THREADS, 2) k_gemm3(float* __restrict__ out) {
    extern __shared__ __half smem[];
    const int tid = threadIdx.x, lane = tid & 31, warp = tid >> 5;
    const int wm = warp & 3, wn = warp >> 2;
    const int nt = blockIdx.x, mt = blockIdx.y, e = blockIdx.z;

    const __half* A = g_hh + (size_t)(e * kTPE + mt * BM) * kF;
    const __half* B = g_w2 + (size_t)e * kF * kH + nt * BN;
    constexpr int NCH = kF / BK;   // 64

    float acc[2][8][4];
#pragma unroll
    for (int i = 0; i < 2; i++)
#pragma unroll
        for (int j = 0; j < 8; j++)
#pragma unroll
            for (int r = 0; r < 4; r++) acc[i][j][r] = 0.f;

#pragma unroll
    for (int c = 0; c < ST3 - 1; c++) {
        __half* sb = smem + c * STG3;
        load_nn(A, kF, B, kH, c * BK, sb, sb + BM * LDSA, tid);
        cp_commit();
    }

    for (int kc = 0; kc < NCH; kc++) {
        cp_wait<ST3 - 2>();
        __syncthreads();
        const int pf = kc + ST3 - 1;
        if (pf < NCH) {
            __half* sb = smem + (pf % ST3) * STG3;
            load_nn(A, kF, B, kH, pf * BK, sb, sb + BM * LDSA, tid);
        }
        cp_commit();
        __half* cs = smem + (kc % ST3) * STG3;
        mma_nn(cs, cs + BM * LDSA, acc, wm, wn, lane);
    }

    const int rBase = e * kTPE + mt * BM + wm * 32 + (lane >> 2);
    const int cBase = nt * BN + wn * 64 + (lane & 3) * 2;
#pragma unroll
    for (int i = 0; i < 2; i++)
#pragma unroll
        for (int j = 0; j < 8; j++) {
            int r = rBase + i * 16;
            int c = cBase + j * 8;
            *reinterpret_cast<float2*>(&out[(size_t)r * kH + c]) =
                make_float2(acc[i][j][0], acc[i][j][1]);
            *reinterpret_cast<float2*>(&out[(size_t)(r + 8) * kH + c]) =
                make_float2(acc[i][j][2], acc[i][j][3]);
        }
}

// ---------------- launch ----------------
extern "C" void kernel_launch(void* const* d_in, const int* in_sizes, int n_in,
                              void* d_out, int out_size) {
    const float* x    = (const float*)d_in[0];
    const float* acts = (const float*)d_in[1];
    const float* wup  = (const float*)d_in[2];
    const float* v1   = (const float*)d_in[3];
    const float* w2   = (const float*)d_in[4];
    float* out = (float*)d_out;

    cudaFuncSetAttribute(k_gemm12, cudaFuncAttributeMaxDynamicSharedMemorySize, SMEM12);
    cudaFuncSetAttribute(k_gemm3,  cudaFuncAttributeMaxDynamicSharedMemorySize, SMEM3);

    k_cvt_all<<<1184, 256>>>(x, acts, wup, v1, w2);

    dim3 g12(kF / BN, kTPE / BM, kE);   // 32 x 8 x 8 = 2048 CTAs
    k_gemm12<<<g12, THREADS, SMEM12>>>();

    dim3 g3(kH / BN, kTPE / BM, kE);    // 8 x 8 x 8 = 512 CTAs
    k_gemm3<<<g3, THREADS, SMEM3>>>(out);
}

// round 8
// speedup vs baseline: 1.1911x; 1.0547x over previous
#include <cuda_runtime.h>
#include <cuda_fp16.h>
#include <stdint.h>

// ---------------- problem constants ----------------
constexpr int kE   = 8;
constexpr int kH   = 1024;
constexpr int kF   = 4096;
constexpr int kDL  = 256;
constexpr int kTPE = 1024;
constexpr int kTok = kE * kTPE;   // 8192

// ---------------- tiling: 128x128 CTAs, 8 warps, 2 CTAs/SM ----------------
constexpr int BM = 128, BN = 128, BK = 64;
constexpr int THREADS = 256;      // 8 warps: 4 (M) x 2 (N), warp tile 32x64
constexpr int ST1 = 3;            // stages gemm12
constexpr int ST3 = 3;            // stages gemm3

constexpr int LDSA  = BK + 8;     // 72 halves per A row
constexpr int LDSB  = BK + 8;     // 72 halves per B row (NT: [n][k])
constexpr int LDSB3 = BN + 8;     // 136 halves per B row (NN: [k][n])

constexpr int STG12 = BM * LDSA + BN * LDSB;   // 18432 halves / stage
constexpr int STG3  = BM * LDSA + BK * LDSB3;  // 17920 halves / stage
constexpr int SMEM12 = ST1 * STG12 * 2;        // 110592 B  (x2 CTA = 221184)
constexpr int SMEM3  = ST3 * STG3  * 2;        // 107520 B  (x2 CTA = 215040)

// ---------------- fp16 scratch (device globals: no allocation allowed) ----------------
__device__ __half g_xh [(size_t)kTok * kH];        // 16 MB
__device__ __half g_ah [(size_t)kTok * kDL];       //  4 MB
__device__ __half g_wup[(size_t)kE * kF * kDL];    // 16 MB
__device__ __half g_v1 [(size_t)kE * kF * kH];     // 64 MB
__device__ __half g_w2 [(size_t)kE * kF * kH];     // 64 MB
__device__ __half g_hh [(size_t)kTok * kF];        // 64 MB  (silu(x1)*x2)

// ---------------- PTX helpers ----------------
__device__ __forceinline__ uint32_t smem_u32(const void* p) {
    uint32_t r;
    asm volatile("{ .reg .u64 t; cvta.to.shared.u64 t, %1; cvt.u32.u64 %0, t; }"
                 : "=r"(r) : "l"(p));
    return r;
}
__device__ __forceinline__ void cp16(uint32_t dst, const void* src) {
    asm volatile("cp.async.cg.shared.global [%0], [%1], 16;" :: "r"(dst), "l"(src));
}
__device__ __forceinline__ void cp_commit() { asm volatile("cp.async.commit_group;"); }
template <int N> __device__ __forceinline__ void cp_wait() {
    asm volatile("cp.async.wait_group %0;" :: "n"(N));
}
__device__ __forceinline__ void ldsm4(uint32_t* r, uint32_t a) {
    asm volatile("ldmatrix.sync.aligned.m8n8.x4.shared.b16 {%0,%1,%2,%3},[%4];"
                 : "=r"(r[0]), "=r"(r[1]), "=r"(r[2]), "=r"(r[3]) : "r"(a));
}
__device__ __forceinline__ void ldsm4t(uint32_t* r, uint32_t a) {
    asm volatile("ldmatrix.sync.aligned.m8n8.x4.trans.shared.b16 {%0,%1,%2,%3},[%4];"
                 : "=r"(r[0]), "=r"(r[1]), "=r"(r[2]), "=r"(r[3]) : "r"(a));
}
__device__ __forceinline__ void mma16816(float* c, const uint32_t* a, uint32_t b0, uint32_t b1) {
    asm volatile(
        "mma.sync.aligned.m16n8k16.row.col.f32.f16.f16.f32 "
        "{%0,%1,%2,%3},{%4,%5,%6,%7},{%8,%9},{%0,%1,%2,%3};"
        : "+f"(c[0]), "+f"(c[1]), "+f"(c[2]), "+f"(c[3])
        : "r"(a[0]), "r"(a[1]), "r"(a[2]), "r"(a[3]), "r"(b0), "r"(b1));
}

// ---------------- fused fp32 -> fp16 conversion (one launch) ----------------
__global__ void k_cvt_all(const float* __restrict__ x, const float* __restrict__ a,
                          const float* __restrict__ wu, const float* __restrict__ v,
                          const float* __restrict__ w) {
    constexpr size_t N1 = (size_t)kTok * kH / 4, N2 = (size_t)kTok * kDL / 4,
                     N3 = (size_t)kE * kF * kDL / 4, N4 = (size_t)kE * kF * kH / 4;
    constexpr size_t C1 = N1, C2 = C1 + N2, C3 = C2 + N3, C4 = C3 + N4, C5 = C4 + N4;
    for (size_t i = (size_t)blockIdx.x * blockDim.x + threadIdx.x; i < C5;
         i += (size_t)gridDim.x * blockDim.x) {
        const float4* s; __half2* d; size_t o;
        if      (i < C1) { s = (const float4*)x;  d = (__half2*)g_xh;  o = i;      }
        else if (i < C2) { s = (const float4*)a;  d = (__half2*)g_ah;  o = i - C1; }
        else if (i < C3) { s = (const float4*)wu; d = (__half2*)g_wup; o = i - C2; }
        else if (i < C4) { s = (const float4*)v;  d = (__half2*)g_v1;  o = i - C3; }
        else             { s = (const float4*)w;  d = (__half2*)g_w2;  o = i - C4; }
        float4 t = s[o];
        d[2 * o]     = __floats2half2_rn(t.x, t.y);
        d[2 * o + 1] = __floats2half2_rn(t.z, t.w);
    }
}

// ---------------- tile loaders (cp.async, 16B vectors, 256 threads) ----------------
__device__ __forceinline__ void load_nt(const __half* gA, int ldA, const __half* gB, int ldB,
                                        int kBase, __half* sA, __half* sB, int tid) {
#pragma unroll
    for (int i = 0; i < 4; i++) {
        int v = tid + i * THREADS;
        int row = v >> 3, c = (v & 7) * 8;
        cp16(smem_u32(sA + row * LDSA + c), gA + (size_t)row * ldA + kBase + c);
    }
#pragma unroll
    for (int i = 0; i < 4; i++) {
        int v = tid + i * THREADS;
        int row = v >> 3, c = (v & 7) * 8;
        cp16(smem_u32(sB + row * LDSB + c), gB + (size_t)row * ldB + kBase + c);
    }
}

__device__ __forceinline__ void load_nn(const __half* gA, int ldA, const __half* gB, int ldB,
                                        int kBase, __half* sA, __half* sB, int tid) {
#pragma unroll
    for (int i = 0; i < 4; i++) {
        int v = tid + i * THREADS;
        int row = v >> 3, c = (v & 7) * 8;
        cp16(smem_u32(sA + row * LDSA + c), gA + (size_t)row * ldA + kBase + c);
    }
#pragma unroll
    for (int i = 0; i < 4; i++) {
        int v = tid + i * THREADS;
        int row = v >> 4, c = (v & 15) * 8;
        cp16(smem_u32(sB + row * LDSB3 + c), gB + (size_t)(kBase + row) * ldB + c);
    }
}

// ---------- software-pipelined warp-tile MMA (32x64), NT variant ----------
__device__ __forceinline__ void mma_nt(const __half* sA, const __half* sB,
                                       float (&acc)[2][8][4], int wm, int wn, int lane) {
    const uint32_t aAddr = smem_u32(sA + (wm * 32 + (lane & 15)) * LDSA + (lane >> 4) * 8);
    const uint32_t bAddr = smem_u32(sB + (wn * 64 + (lane & 7) + ((lane >> 4) << 3)) * LDSB
                                       + ((lane >> 3) & 1) * 8);
    uint32_t a_cur[2][4], a_nxt[2][4], b_cur[4], b_nxt[4];
    ldsm4(a_cur[0], aAddr);
    ldsm4(a_cur[1], aAddr + 16 * LDSA * 2);
    ldsm4(b_cur, bAddr);
#pragma unroll
    for (int k = 0; k < 4; k++) {
#pragma unroll
        for (int j = 0; j < 4; j++) {
            // prefetch next fragments before consuming current ones
            if (j < 3) {
                ldsm4(b_nxt, bAddr + k * 32 + (j + 1) * 16 * LDSB * 2);
            } else if (k < 3) {
                ldsm4(a_nxt[0], aAddr + (k + 1) * 32);
                ldsm4(a_nxt[1], aAddr + (k + 1) * 32 + 16 * LDSA * 2);
                ldsm4(b_nxt, bAddr + (k + 1) * 32);
            }
            mma16816(acc[0][2 * j],     a_cur[0], b_cur[0], b_cur[1]);
            mma16816(acc[1][2 * j],     a_cur[1], b_cur[0], b_cur[1]);
            mma16816(acc[0][2 * j + 1], a_cur[0], b_cur[2], b_cur[3]);
            mma16816(acc[1][2 * j + 1], a_cur[1], b_cur[2], b_cur[3]);
#pragma unroll
            for (int r = 0; r < 4; r++) b_cur[r] = b_nxt[r];
            if (j == 3 && k < 3) {
#pragma unroll
                for (int im = 0; im < 2; im++)
#pragma unroll
                    for (int r = 0; r < 4; r++) a_cur[im][r] = a_nxt[im][r];
            }
        }
    }
}

// ---------- software-pipelined warp-tile MMA (32x64), NN variant ----------
__device__ __forceinline__ void mma_nn(const __half* sA, const __half* sB,
                                       float (&acc)[2][8][4], int wm, int wn, int lane) {
    const uint32_t aAddr = smem_u32(sA + (wm * 32 + (lane & 15)) * LDSA + (lane >> 4) * 8);
    const uint32_t bAddr = smem_u32(sB + ((lane & 7) + ((lane >> 3) & 1) * 8) * LDSB3
                                       + wn * 64 + (lane >> 4) * 8);
    // B(k,j) at bAddr + k*16*LDSB3*2 + j*32
    uint32_t a_cur[2][4], a_nxt[2][4], b_cur[4], b_nxt[4];
    ldsm4(a_cur[0], aAddr);
    ldsm4(a_cur[1], aAddr + 16 * LDSA * 2);
    ldsm4t(b_cur, bAddr);
#pragma unroll
    for (int k = 0; k < 4; k++) {
#pragma unroll
        for (int j = 0; j < 4; j++) {
            if (j < 3) {
                ldsm4t(b_nxt, bAddr + k * 16 * LDSB3 * 2 + (j + 1) * 32);
            } else if (k < 3) {
                ldsm4(a_nxt[0], aAddr + (k + 1) * 32);
                ldsm4(a_nxt[1], aAddr + (k + 1) * 32 + 16 * LDSA * 2);
                ldsm4t(b_nxt, bAddr + (k + 1) * 16 * LDSB3 * 2);
            }
            mma16816(acc[0][2 * j],     a_cur[0], b_cur[0], b_cur[1]);
            mma16816(acc[1][2 * j],     a_cur[1], b_cur[0], b_cur[1]);
            mma16816(acc[0][2 * j + 1], a_cur[0], b_cur[2], b_cur[3]);
            mma16816(acc[1][2 * j + 1], a_cur[1], b_cur[2], b_cur[3]);
#pragma unroll
            for (int r = 0; r < 4; r++) b_cur[r] = b_nxt[r];
            if (j == 3 && k < 3) {
#pragma unroll
                for (int im = 0; im < 2; im++)
#pragma unroll
                    for (int r = 0; r < 4; r++) a_cur[im][r] = a_nxt[im][r];
            }
        }
    }
}

// ==================== kernel 1: x1=acts@wup^T, x2=x@v1^T, h=silu(x1)*x2 ===========
__global__ void __launch_bounds__(THREADS, 2) k_gemm12() {
    extern __shared__ __half smem[];
    const int tid = threadIdx.x, lane = tid & 31, warp = tid >> 5;
    const int wm = warp & 3, wn = warp >> 2;
    const int nt = blockIdx.x, mt = blockIdx.y, e = blockIdx.z;

    const __half* A1 = g_ah  + (size_t)(e * kTPE + mt * BM) * kDL;
    const __half* B1 = g_wup + ((size_t)e * kF + nt * BN) * kDL;
    const __half* A2 = g_xh  + (size_t)(e * kTPE + mt * BM) * kH;
    const __half* B2 = g_v1  + ((size_t)e * kF + nt * BN) * kH;

    constexpr int NCH1 = kDL / BK;          // 4
    constexpr int NCH  = NCH1 + kH / BK;    // 20

    auto srcOf = [&](int c, const __half*& A, const __half*& B, int& la, int& lb, int& ko) {
        if (c < NCH1) { A = A1; B = B1; la = kDL; lb = kDL; ko = c * BK; }
        else          { A = A2; B = B2; la = kH;  lb = kH;  ko = (c - NCH1) * BK; }
    };

    float acc[2][8][4];
#pragma unroll
    for (int i = 0; i < 2; i++)
#pragma unroll
        for (int j = 0; j < 8; j++)
#pragma unroll
            for (int r = 0; r < 4; r++) acc[i][j][r] = 0.f;
    __half2 sf[2][8][2];

#pragma unroll
    for (int c = 0; c < ST1 - 1; c++) {
        const __half *A, *B; int la, lb, ko;
        srcOf(c, A, B, la, lb, ko);
        __half* sb = smem + c * STG12;
        load_nt(A, la, B, lb, ko, sb, sb + BM * LDSA, tid);
        cp_commit();
    }

    for (int kc = 0; kc < NCH; kc++) {
        cp_wait<ST1 - 2>();
        __syncthreads();
        const int pf = kc + ST1 - 1;
        if (pf < NCH) {
            const __half *A, *B; int la, lb, ko;
            srcOf(pf, A, B, la, lb, ko);
            __half* sb = smem + (pf % ST1) * STG12;
            load_nt(A, la, B, lb, ko, sb, sb + BM * LDSA, tid);
        }
        cp_commit();

        if (kc == NCH1) {
#pragma unroll
            for (int i = 0; i < 2; i++)
#pragma unroll
                for (int j = 0; j < 8; j++) {
#pragma unroll
                    for (int p = 0; p < 2; p++) {
                        float x0 = acc[i][j][2 * p], x1 = acc[i][j][2 * p + 1];
                        sf[i][j][p] = __floats2half2_rn(x0 / (1.f + __expf(-x0)),
                                                        x1 / (1.f + __expf(-x1)));
                    }
                    acc[i][j][0] = acc[i][j][1] = acc[i][j][2] = acc[i][j][3] = 0.f;
                }
        }

        __half* cs = smem + (kc % ST1) * STG12;
        mma_nt(cs, cs + BM * LDSA, acc, wm, wn, lane);
    }

    const int rBase = e * kTPE + mt * BM + wm * 32 + (lane >> 2);
    const int cBase = nt * BN + wn * 64 + (lane & 3) * 2;
#pragma unroll
    for (int i = 0; i < 2; i++)
#pragma unroll
        for (int j = 0; j < 8; j++) {
            int r = rBase + i * 16;
            int c = cBase + j * 8;
            float2 s0 = __half22float2(sf[i][j][0]);
            float2 s1 = __half22float2(sf[i][j][1]);
            __half2 h0 = __floats2half2_rn(s0.x * acc[i][j][0], s0.y * acc[i][j][1]);
            __half2 h1 = __floats2half2_rn(s1.x * acc[i][j][2], s1.y * acc[i][j][3]);
            *reinterpret_cast<__half2*>(&g_hh[(size_t)r * kF + c])       = h0;
            *reinterpret_cast<__half2*>(&g_hh[(size_t)(r + 8) * kF + c]) = h1;
        }
}

// ==================== kernel 2: out = h @ w2 (NN) ====================
__global__ void __launch_bounds__(THREADS, 2) k_gemm3(float* __restrict__ out) {
    extern __shared__ __half smem[];
    const int tid = threadIdx.x, lane = tid & 31, warp = tid >> 5;
    const int wm = warp & 3, wn = warp >> 2;
    const int nt = blockIdx.x, mt = blockIdx.y, e = blockIdx.z;

    const __half* A = g_hh + (size_t)(e * kTPE + mt * BM) * kF;
    const __half* B = g_w2 + (size_t)e * kF * kH + nt * BN;
    constexpr int NCH = kF / BK;   // 64

    float acc[2][8][4];
#pragma unroll
    for (int i = 0; i < 2; i++)
#pragma unroll
        for (int j = 0; j < 8; j++)
#pragma unroll
            for (int r = 0; r < 4; r++) acc[i][j][r] = 0.f;

#pragma unroll
    for (int c = 0; c < ST3 - 1; c++) {
        __half* sb = smem + c * STG3;
        load_nn(A, kF, B, kH, c * BK, sb, sb + BM * LDSA, tid);
        cp_commit();
    }

    for (int kc = 0; kc < NCH; kc++) {
        cp_wait<ST3 - 2>();
        __syncthreads();
        const int pf = kc + ST3 - 1;
        if (pf < NCH) {
            __half* sb = smem + (pf % ST3) * STG3;
            load_nn(A, kF, B, kH, pf * BK, sb, sb + BM * LDSA, tid);
        }
        cp_commit();
        __half* cs = smem + (kc % ST3) * STG3;
        mma_nn(cs, cs + BM * LDSA, acc, wm, wn, lane);
    }

    const int rBase = e * kTPE + mt * BM + wm * 32 + (lane >> 2);
    const int cBase = nt * BN + wn * 64 + (lane & 3) * 2;
#pragma unroll
    for (int i = 0; i < 2; i++)
#pragma unroll
        for (int j = 0; j < 8; j++) {
            int r = rBase + i * 16;
            int c = cBase + j * 8;
            *reinterpret_cast<float2*>(&out[(size_t)r * kH + c]) =
                make_float2(acc[i][j][0], acc[i][j][1]);
            *reinterpret_cast<float2*>(&out[(size_t)(r + 8) * kH + c]) =
                make_float2(acc[i][j][2], acc[i][j][3]);
        }
}

// ---------------- launch ----------------
extern "C" void kernel_launch(void* const* d_in, const int* in_sizes, int n_in,
                              void* d_out, int out_size) {
    const float* x    = (const float*)d_in[0];
    const float* acts = (const float*)d_in[1];
    const float* wup  = (const float*)d_in[2];
    const float* v1   = (const float*)d_in[3];
    const float* w2   = (const float*)d_in[4];
    float* out = (float*)d_out;

    cudaFuncSetAttribute(k_gemm12, cudaFuncAttributeMaxDynamicSharedMemorySize, SMEM12);
    cudaFuncSetAttribute(k_gemm3,  cudaFuncAttributeMaxDynamicSharedMemorySize, SMEM3);

    k_cvt_all<<<1184, 256>>>(x, acts, wup, v1, w2);

    dim3 g12(kF / BN, kTPE / BM, kE);   // 32 x 8 x 8 = 2048 CTAs
    k_gemm12<<<g12, THREADS, SMEM12>>>();

    dim3 g3(kH / BN, kTPE / BM, kE);    // 8 x 8 x 8 = 512 CTAs
    k_gemm3<<<g3, THREADS, SMEM3>>>(out);
}